// round 6
// baseline (speedup 1.0000x reference)
#include <cuda_runtime.h>
#include <cuda_bf16.h>
#include <cstdint>

#define N_FEAT    128
#define N_CLUS    64
#define TILE_M    128
#define THREADS   256
#define GRID_MAIN 148
#define EPS       1.0f
#define NEGINF    (-3.4e38f)

// smem layout (bytes)
#define OFF_STAGE 0          // 4 slots * 32768B  (64 rows * 512B fp32, swizzled)
#define OFF_XHI   131072     // 2 bufs * 32768B   (128 rows * 256B bf16, swizzled)
#define OFF_BHI   196608     // 64 rows * 256B bf16, swizzled
#define OFF_X2    212992     // 2 * 128 floats
#define OFF_BEST  214016     // 64 u64 exact keys
#define SMEM_TOTAL 214528

__device__ unsigned long long g_part[GRID_MAIN * N_CLUS];

// ---------------- helpers ----------------
__device__ __forceinline__ uint32_t smem_u32(const void* p) {
    return (uint32_t)__cvta_generic_to_shared(p);
}
__device__ __forceinline__ uint32_t cvt_bf2(float hi, float lo) {
    uint32_t d;
    asm("cvt.rn.bf16x2.f32 %0, %1, %2;" : "=r"(d) : "f"(hi), "f"(lo)); // low half = lo
    return d;
}
__device__ __forceinline__ uint32_t orderf(float f) {
    uint32_t u = __float_as_uint(f);
    return u ^ (((uint32_t)((int32_t)u >> 31)) | 0x80000000u);
}
__device__ __forceinline__ float inv_orderf(uint32_t k) {
    uint32_t u = (k & 0x80000000u) ? (k ^ 0x80000000u) : ~k;
    return __uint_as_float(u);
}
__device__ __forceinline__ void sts128(uint32_t a, uint32_t x, uint32_t y, uint32_t z, uint32_t w) {
    asm volatile("st.shared.v4.b32 [%0], {%1,%2,%3,%4};" :: "r"(a), "r"(x), "r"(y), "r"(z), "r"(w) : "memory");
}
__device__ __forceinline__ void lds128(float& x, float& y, float& z, float& w, uint32_t a) {
    asm volatile("ld.shared.v4.f32 {%0,%1,%2,%3}, [%4];"
                 : "=f"(x), "=f"(y), "=f"(z), "=f"(w) : "r"(a));
}
__device__ __forceinline__ uint32_t lds32v(uint32_t a) {
    uint32_t d;
    asm volatile("ld.volatile.shared.b32 %0, [%1];" : "=r"(d) : "r"(a));
    return d;
}
__device__ __forceinline__ void ldm4(uint32_t& r0, uint32_t& r1, uint32_t& r2, uint32_t& r3, uint32_t a) {
    asm volatile("ldmatrix.sync.aligned.m8n8.x4.shared.b16 {%0,%1,%2,%3}, [%4];"
                 : "=r"(r0), "=r"(r1), "=r"(r2), "=r"(r3) : "r"(a));
}
__device__ __forceinline__ void mma16816(float& c0, float& c1, float& c2, float& c3,
                                         uint32_t a0, uint32_t a1, uint32_t a2, uint32_t a3,
                                         uint32_t b0, uint32_t b1) {
    asm volatile("mma.sync.aligned.m16n8k16.row.col.f32.bf16.bf16.f32 "
                 "{%0,%1,%2,%3},{%4,%5,%6,%7},{%8,%9},{%0,%1,%2,%3};"
                 : "+f"(c0), "+f"(c1), "+f"(c2), "+f"(c3)
                 : "r"(a0), "r"(a1), "r"(a2), "r"(a3), "r"(b0), "r"(b1));
}
__device__ __forceinline__ void cp16(uint32_t s, const void* g) {
    asm volatile("cp.async.cg.shared.global [%0], [%1], 16;" :: "r"(s), "l"(g));
}
__device__ __forceinline__ void cp_commit() { asm volatile("cp.async.commit_group;"); }
__device__ __forceinline__ void cp_wait2()  { asm volatile("cp.async.wait_group 2;" ::: "memory"); }

extern __shared__ char smem[];

// prefetch one 64-row half tile (half=0/1) of tile t into ring slot
__device__ __forceinline__ void prefetch_half(const float* __restrict__ x, int t, int NT,
                                              int n_tokens, int slot, int half,
                                              int tid, uint32_t sb) {
    if (t < NT) {
        const int base = t * TILE_M + half * 64;
#pragma unroll
        for (int c = 0; c < 8; ++c) {
            int chunk = tid + c * THREADS;      // 0..2047
            int r = chunk >> 5, q = chunk & 31; // row 0..63, 16B chunk
            if (base + r < n_tokens)
                cp16(sb + (uint32_t)(OFF_STAGE + slot * 32768 + r * 512 + ((q ^ (r & 31)) << 4)),
                     x + (size_t)(base + r) * N_FEAT + q * 4);
        }
    }
    cp_commit();
}

// exact warp-cooperative rescore from GLOBAL memory (L2-hot); rare
__device__ __forceinline__ void warp_rescore_g(const float* __restrict__ x,
                                               const float* __restrict__ cc,
                                               int token, int cl, float x2,
                                               int lane, unsigned long long* bestk) {
    float4 xv = __ldg((const float4*)(x + (size_t)token * N_FEAT) + lane);
    float4 cv = __ldg((const float4*)(cc + (size_t)cl * N_FEAT) + lane);
    float d = xv.x * cv.x + xv.y * cv.y + xv.z * cv.z + xv.w * cv.w;
#pragma unroll
    for (int o = 16; o >= 1; o >>= 1)
        d += __shfl_xor_sync(0xFFFFFFFFu, d, o);
    if (lane == 0) {
        float s = d - 0.5f * x2;
        unsigned long long key =
            ((unsigned long long)orderf(s) << 32) |
            (unsigned long long)(0xFFFFFFFFu - (uint32_t)token);
        atomicMax(&bestk[cl], key);
    }
}

__global__ void __launch_bounds__(THREADS, 1)
cluster_hmma(const float* __restrict__ x, const float* __restrict__ cc, int n_tokens)
{
    const int tid  = threadIdx.x;
    const int lane = tid & 31;
    const int wid  = tid >> 5;
    const int mg   = wid >> 1;     // m-group: rows [mg*32, mg*32+32)
    const int nh   = wid & 1;      // n-half:  cols [nh*32, nh*32+32)
    const int bid  = blockIdx.x;
    const uint32_t sb = smem_u32(smem);
    const int NT = (n_tokens + TILE_M - 1) / TILE_M;

    const int crow = tid >> 1, chalf = tid & 1;   // convert mapping: 2 threads/row

    // depth-2 prefetch: tile bid -> slots 0,1 ; tile bid+G -> slots 2,3
    prefetch_half(x, bid,             NT, n_tokens, 0, 0, tid, sb);
    prefetch_half(x, bid,             NT, n_tokens, 1, 1, tid, sb);
    prefetch_half(x, bid + GRID_MAIN, NT, n_tokens, 2, 0, tid, sb);
    prefetch_half(x, bid + GRID_MAIN, NT, n_tokens, 3, 1, tid, sb);

    // ---- centers bf16-hi swizzled in smem ----
#pragma unroll
    for (int i = tid; i < N_CLUS * 16; i += THREADS) {   // 16 chunks of 8 per row
        int n = i >> 4, kc = i & 15;
        const float4* cp = (const float4*)(cc + n * N_FEAT + kc * 8);
        float4 ca = cp[0], cb = cp[1];
        uint32_t h0 = cvt_bf2(ca.y, ca.x), h1 = cvt_bf2(ca.w, ca.z);
        uint32_t h2 = cvt_bf2(cb.y, cb.x), h3 = cvt_bf2(cb.w, cb.z);
        uint32_t off = (uint32_t)(n * 256 + ((kc * 16) ^ ((n & 7) << 4)));
        sts128(sb + OFF_BHI + off, h0, h1, h2, h3);
    }

    unsigned long long* bestk = (unsigned long long*)(smem + OFF_BEST);
    float* x2s = (float*)(smem + OFF_X2);

    // ---- seed every cluster with one exact score (from gmem, L2-hot) ----
    {
        int token = bid * TILE_M + wid;
        if (token < n_tokens) {
            float4 xv = __ldg((const float4*)(x + (size_t)token * N_FEAT) + lane);
            float s2 = xv.x * xv.x + xv.y * xv.y + xv.z * xv.z + xv.w * xv.w;
#pragma unroll
            for (int o = 16; o >= 1; o >>= 1)
                s2 += __shfl_xor_sync(0xFFFFFFFFu, s2, o);
#pragma unroll
            for (int j = 0; j < 8; ++j) {
                int cl = wid * 8 + j;
                float4 cv = __ldg((const float4*)(cc + (size_t)cl * N_FEAT) + lane);
                float d = xv.x * cv.x + xv.y * cv.y + xv.z * cv.z + xv.w * cv.w;
#pragma unroll
                for (int o = 16; o >= 1; o >>= 1)
                    d += __shfl_xor_sync(0xFFFFFFFFu, d, o);
                if (lane == 0) {
                    float s = d - 0.5f * s2;
                    bestk[cl] = ((unsigned long long)orderf(s) << 32) |
                                (unsigned long long)(0xFFFFFFFFu - (uint32_t)token);
                }
            }
        } else if (lane < 8) {
            bestk[wid * 8 + lane] = 0ull;
        }
    }
    __syncthreads();

    // ---- preload Bhi fragments into registers (constant across all tiles) ----
    const int lr = (lane & 7) | (lane & 8);    // ldmatrix row-within-16
    const int lk = lane & 16;                  // 16B column select
    const uint32_t sw = (uint32_t)((lr & 7) << 4);
    const int nb = nh * 32;

    uint32_t bhi[8][4][2];
#pragma unroll
    for (int ks = 0; ks < 8; ++ks) {
#pragma unroll
        for (int np = 0; np < 2; ++np) {
            uint32_t addr = sb + OFF_BHI + (uint32_t)((nb + np * 16 + lr) * 256)
                          + (((uint32_t)(ks * 32 + lk)) ^ sw);
            uint32_t r0, r1, r2, r3;
            ldm4(r0, r1, r2, r3, addr);
            bhi[ks][np * 2][0] = r0;  bhi[ks][np * 2 + 1][0] = r1;
            bhi[ks][np * 2][1] = r2;  bhi[ks][np * 2 + 1][1] = r3;
        }
    }

    uint32_t aAh[2];
#pragma unroll
    for (int mi = 0; mi < 2; ++mi)
        aAh[mi] = sb + OFF_XHI + (uint32_t)((mg * 32 + mi * 16 + lr) * 256);

    int it = 0;
    for (int t = bid; t < NT; t += GRID_MAIN, ++it) {
        const int base = t * TILE_M;
        const uint32_t xoff = (uint32_t)(it & 1) << 15;   // XHI buffer
        const int x2o = (it & 1) * TILE_M;

        cp_wait2();           // tile `it` (2 oldest groups) landed
        __syncthreads();      // (a) stage visible CTA-wide; XHI[it&1]/x2s free (MMA it-2 done)

        // ---- convert: stage fp32 -> bf16-hi XHI[it&1] + |x|^2 ----
        {
            const bool val = (base + crow) < n_tokens;
            const int sl = (2 * it + (crow >> 6)) & 3;
            const int r  = crow & 63;
            const uint32_t rowb = sb + (uint32_t)(OFF_STAGE + sl * 32768 + r * 512);
            const int rsw = r & 31;
            float s = 0.f;
#pragma unroll
            for (int j = 0; j < 8; ++j) {
                float4 a, b;
                lds128(a.x, a.y, a.z, a.w, rowb + (uint32_t)(((chalf * 16 + 2 * j) ^ rsw) << 4));
                lds128(b.x, b.y, b.z, b.w, rowb + (uint32_t)(((chalf * 16 + 2 * j + 1) ^ rsw) << 4));
                if (!val) { a = make_float4(0.f, 0.f, 0.f, 0.f); b = a; }
                uint32_t h0 = cvt_bf2(a.y, a.x), h1 = cvt_bf2(a.w, a.z);
                uint32_t h2 = cvt_bf2(b.y, b.x), h3 = cvt_bf2(b.w, b.z);
                s += a.x * a.x + a.y * a.y + a.z * a.z + a.w * a.w;
                s += b.x * b.x + b.y * b.y + b.z * b.z + b.w * b.w;
                uint32_t off = (uint32_t)(crow * 256 + (((chalf * 8 + j) * 16) ^ ((crow & 7) << 4)));
                sts128(sb + OFF_XHI + xoff + off, h0, h1, h2, h3);
            }
            s += __shfl_xor_sync(0xFFFFFFFFu, s, 1);
            if (chalf == 0) x2s[x2o + crow] = s;
        }
        __syncthreads();      // (b) XHI/x2s ready; all convert reads of slots done

        // prefetch tile t+2G into the slots this tile just freed
        prefetch_half(x, t + 2 * GRID_MAIN, NT, n_tokens, (2 * it) & 3,     0, tid, sb);
        prefetch_half(x, t + 2 * GRID_MAIN, NT, n_tokens, (2 * it + 1) & 3, 1, tid, sb);

        // ---- MMA: hh term only ----
        float c[2][4][4];
#pragma unroll
        for (int mi = 0; mi < 2; ++mi)
#pragma unroll
            for (int ni = 0; ni < 4; ++ni)
#pragma unroll
                for (int r = 0; r < 4; ++r) c[mi][ni][r] = 0.f;

#pragma unroll
        for (int ks = 0; ks < 8; ++ks) {
            const uint32_t ko = ((uint32_t)(ks * 32 + lk)) ^ sw;
            uint32_t ah[2][4];
#pragma unroll
            for (int mi = 0; mi < 2; ++mi)
                ldm4(ah[mi][0], ah[mi][1], ah[mi][2], ah[mi][3], aAh[mi] + xoff + ko);
#pragma unroll
            for (int mi = 0; mi < 2; ++mi)
#pragma unroll
                for (int ni = 0; ni < 4; ++ni)
                    mma16816(c[mi][ni][0], c[mi][ni][1], c[mi][ni][2], c[mi][ni][3],
                             ah[mi][0], ah[mi][1], ah[mi][2], ah[mi][3],
                             bhi[ks][ni][0], bhi[ks][ni][1]);
        }

        // ---- epilogue: scores, threshold vs exact best, rescue ----
        float h2v[2][2];
        bool vld[2][2];
#pragma unroll
        for (int mi = 0; mi < 2; ++mi)
#pragma unroll
            for (int p = 0; p < 2; ++p) {
                int row = mg * 32 + mi * 16 + (lane >> 2) + p * 8;
                h2v[mi][p] = 0.5f * x2s[x2o + row];
                vld[mi][p] = (base + row) < n_tokens;
            }

#pragma unroll
        for (int mi = 0; mi < 2; ++mi)
#pragma unroll
            for (int ni = 0; ni < 4; ++ni)
#pragma unroll
                for (int p = 0; p < 2; ++p)
#pragma unroll
                    for (int ci = 0; ci < 2; ++ci) {
                        float sc = c[mi][ni][ci + 2 * p] - h2v[mi][p];
                        c[mi][ni][ci + 2 * p] = vld[mi][p] ? sc : NEGINF;
                    }

        float thrf[4][2];
#pragma unroll
        for (int ni = 0; ni < 4; ++ni)
#pragma unroll
            for (int ci = 0; ci < 2; ++ci) {
                int cl = nb + ni * 8 + (lane & 3) * 2 + ci;
                uint32_t hi = lds32v(sb + (uint32_t)(OFF_BEST + cl * 8 + 4));
                thrf[ni][ci] = inv_orderf(hi) - EPS;    // seeded => always finite
            }

        uint32_t myMask = 0;
#pragma unroll
        for (int ni = 0; ni < 4; ++ni)
#pragma unroll
            for (int ci = 0; ci < 2; ++ci)
#pragma unroll
                for (int p = 0; p < 2; ++p)
#pragma unroll
                    for (int mi = 0; mi < 2; ++mi)
                        if (c[mi][ni][ci + 2 * p] >= thrf[ni][ci])
                            myMask |= 1u << ((ni << 3) | (ci << 2) | (p << 1) | mi);

        uint32_t active = __ballot_sync(0xFFFFFFFFu, myMask != 0);
        while (active) {
            int src = __ffs(active) - 1;
            active &= active - 1;
            uint32_t m = __shfl_sync(0xFFFFFFFFu, myMask, src);
            while (m) {
                int b = __ffs(m) - 1;
                m &= m - 1;
                int mi = b & 1, p = (b >> 1) & 1, ci = (b >> 2) & 1, ni = b >> 3;
                int row = mg * 32 + mi * 16 + (src >> 2) + p * 8;
                int cl  = nb + ni * 8 + (src & 3) * 2 + ci;
                warp_rescore_g(x, cc, base + row, cl, x2s[x2o + row], lane, bestk);
            }
        }
        // no trailing barrier: next iter's bar(a) provides the separation
    }

    __syncthreads();
    if (tid < N_CLUS)
        g_part[(size_t)bid * N_CLUS + tid] = bestk[tid];
}

// ---------------- gather: reduce partials, copy winning rows ----------------
__global__ void gather_k(const float* __restrict__ x, float* __restrict__ out) {
    __shared__ unsigned long long red[256];
    const int c = blockIdx.x, tid = threadIdx.x;
    unsigned long long v = 0ull;
    if (tid < GRID_MAIN) v = g_part[(size_t)tid * N_CLUS + c];
    red[tid] = v;
    __syncthreads();
#pragma unroll
    for (int s = 128; s > 0; s >>= 1) {
        if (tid < s) { unsigned long long o = red[tid + s]; if (o > red[tid]) red[tid] = o; }
        __syncthreads();
    }
    unsigned int gi = 0xFFFFFFFFu - (unsigned int)(red[0] & 0xFFFFFFFFull);
    if (tid < N_FEAT)
        out[c * N_FEAT + tid] = x[(size_t)gi * N_FEAT + tid];
}

// ---------------- launch ----------------
extern "C" void kernel_launch(void* const* d_in, const int* in_sizes, int n_in,
                              void* d_out, int out_size)
{
    const float* x  = (const float*)d_in[0];
    const float* cc = (const float*)d_in[1];
    int n_tokens = in_sizes[0] / N_FEAT;

    cudaFuncSetAttribute(cluster_hmma, cudaFuncAttributeMaxDynamicSharedMemorySize, SMEM_TOTAL);
    cluster_hmma<<<GRID_MAIN, THREADS, SMEM_TOTAL>>>(x, cc, n_tokens);
    gather_k<<<N_CLUS, 256>>>(x, (float*)d_out);
}

// round 8
// speedup vs baseline: 1.5325x; 1.5325x over previous
#include <cuda_runtime.h>
#include <cuda_bf16.h>
#include <cstdint>

#define N_FEAT    128
#define N_CLUS    64
#define TILE_M    128
#define THREADS   256
#define GRID_MAIN 148
#define EPS       1.0f
#define NEGINF    (-3.4e38f)

// smem layout (bytes)
#define OFF_XHI   0          // 128 rows * 256B bf16 (hi), swizzled
#define OFF_BHI   32768      // 64 rows * 256B bf16 (hi), swizzled
#define OFF_CCF   49152      // 64 * 128 fp32 centers, linear
#define OFF_X2    81920      // 128 floats
#define OFF_BEST  82432      // 64 u64 exact keys
#define SMEM_TOTAL 82944

__device__ unsigned long long g_part[GRID_MAIN * N_CLUS];

// ---------------- helpers ----------------
__device__ __forceinline__ uint32_t smem_u32(const void* p) {
    return (uint32_t)__cvta_generic_to_shared(p);
}
__device__ __forceinline__ uint32_t cvt_bf2(float hi, float lo) {
    uint32_t d;
    asm("cvt.rn.bf16x2.f32 %0, %1, %2;" : "=r"(d) : "f"(hi), "f"(lo)); // low half = lo
    return d;
}
__device__ __forceinline__ uint32_t orderf(float f) {
    uint32_t u = __float_as_uint(f);
    return u ^ (((uint32_t)((int32_t)u >> 31)) | 0x80000000u);
}
__device__ __forceinline__ float inv_orderf(uint32_t k) {
    uint32_t u = (k & 0x80000000u) ? (k ^ 0x80000000u) : ~k;
    return __uint_as_float(u);
}
__device__ __forceinline__ void sts128(uint32_t a, uint32_t x, uint32_t y, uint32_t z, uint32_t w) {
    asm volatile("st.shared.v4.b32 [%0], {%1,%2,%3,%4};" :: "r"(a), "r"(x), "r"(y), "r"(z), "r"(w) : "memory");
}
__device__ __forceinline__ void lds128(float& x, float& y, float& z, float& w, uint32_t a) {
    asm volatile("ld.shared.v4.f32 {%0,%1,%2,%3}, [%4];"
                 : "=f"(x), "=f"(y), "=f"(z), "=f"(w) : "r"(a));
}
__device__ __forceinline__ uint32_t lds32v(uint32_t a) {
    uint32_t d;
    asm volatile("ld.volatile.shared.b32 %0, [%1];" : "=r"(d) : "r"(a));
    return d;
}
__device__ __forceinline__ void ldm4(uint32_t& r0, uint32_t& r1, uint32_t& r2, uint32_t& r3, uint32_t a) {
    asm volatile("ldmatrix.sync.aligned.m8n8.x4.shared.b16 {%0,%1,%2,%3}, [%4];"
                 : "=r"(r0), "=r"(r1), "=r"(r2), "=r"(r3) : "r"(a));
}
__device__ __forceinline__ void mma16816(float& c0, float& c1, float& c2, float& c3,
                                         uint32_t a0, uint32_t a1, uint32_t a2, uint32_t a3,
                                         uint32_t b0, uint32_t b1) {
    asm volatile("mma.sync.aligned.m16n8k16.row.col.f32.bf16.bf16.f32 "
                 "{%0,%1,%2,%3},{%4,%5,%6,%7},{%8,%9},{%0,%1,%2,%3};"
                 : "+f"(c0), "+f"(c1), "+f"(c2), "+f"(c3)
                 : "r"(a0), "r"(a1), "r"(a2), "r"(a3), "r"(b0), "r"(b1));
}

extern __shared__ char smem[];

// exact warp-cooperative rescore: x row from global (L1-hot), center from smem fp32
__device__ __forceinline__ void warp_rescore(const float* __restrict__ x, uint32_t sb,
                                             int token, int cl, float x2,
                                             int lane, unsigned long long* bestk) {
    float4 xv = __ldg((const float4*)(x + (size_t)token * N_FEAT) + lane);
    float4 cv;
    lds128(cv.x, cv.y, cv.z, cv.w, sb + (uint32_t)(OFF_CCF + cl * 512 + (lane << 4)));
    float d = xv.x * cv.x + xv.y * cv.y + xv.z * cv.z + xv.w * cv.w;
#pragma unroll
    for (int o = 16; o >= 1; o >>= 1)
        d += __shfl_xor_sync(0xFFFFFFFFu, d, o);
    if (lane == 0) {
        float s = d - 0.5f * x2;
        unsigned long long key =
            ((unsigned long long)orderf(s) << 32) |
            (unsigned long long)(0xFFFFFFFFu - (uint32_t)token);
        atomicMax(&bestk[cl], key);
    }
}

__global__ void __launch_bounds__(THREADS, 1)
cluster_hmma(const float* __restrict__ x, const float* __restrict__ cc, int n_tokens)
{
    const int tid  = threadIdx.x;
    const int lane = tid & 31;
    const int wid  = tid >> 5;
    const int mg   = wid >> 1;     // m-group: rows [mg*32, mg*32+32)
    const int nh   = wid & 1;      // n-half:  cols [nh*32, nh*32+32)
    const int bid  = blockIdx.x;
    const uint32_t sb = smem_u32(smem);
    const int NT = (n_tokens + TILE_M - 1) / TILE_M;

    const int crow = tid >> 1, chalf = tid & 1;   // convert mapping: 2 threads/row (half-row each)

    float4 v[16];
#define LOADV(tt) do { \
        long grow_ = (long)(tt) * TILE_M + crow; \
        bool val_ = ((tt) < NT) && (grow_ < (long)n_tokens); \
        const float4* gp_ = (const float4*)(x + (size_t)grow_ * N_FEAT) + chalf * 16; \
        _Pragma("unroll") \
        for (int j_ = 0; j_ < 16; ++j_) \
            v[j_] = val_ ? __ldg(gp_ + j_) : make_float4(0.f, 0.f, 0.f, 0.f); \
    } while (0)

    // prologue: start loading tile `bid` into registers immediately
    LOADV(bid);

    // ---- centers: bf16-hi swizzled + fp32 copy ----
#pragma unroll
    for (int i = tid; i < N_CLUS * 16; i += THREADS) {   // 16 chunks of 8 floats per row
        int n = i >> 4, kc = i & 15;
        const float4* cp = (const float4*)(cc + n * N_FEAT + kc * 8);
        float4 ca = cp[0], cb = cp[1];
        uint32_t h0 = cvt_bf2(ca.y, ca.x), h1 = cvt_bf2(ca.w, ca.z);
        uint32_t h2 = cvt_bf2(cb.y, cb.x), h3 = cvt_bf2(cb.w, cb.z);
        uint32_t off = (uint32_t)(n * 256 + ((kc * 16) ^ ((n & 7) << 4)));
        sts128(sb + OFF_BHI + off, h0, h1, h2, h3);
    }
    {
        const float4* c4 = (const float4*)cc;
        float4* f4 = (float4*)(smem + OFF_CCF);
        for (int i = tid; i < N_CLUS * N_FEAT / 4; i += THREADS)
            f4[i] = c4[i];
    }

    unsigned long long* bestk = (unsigned long long*)(smem + OFF_BEST);
    float* x2s = (float*)(smem + OFF_X2);

    // ---- seed every cluster with one exact score ----
    {
        int token = bid * TILE_M + wid;
        if (token < n_tokens) {
            float4 xv = __ldg((const float4*)(x + (size_t)token * N_FEAT) + lane);
            float s2 = xv.x * xv.x + xv.y * xv.y + xv.z * xv.z + xv.w * xv.w;
#pragma unroll
            for (int o = 16; o >= 1; o >>= 1)
                s2 += __shfl_xor_sync(0xFFFFFFFFu, s2, o);
#pragma unroll
            for (int j = 0; j < 8; ++j) {
                int cl = wid * 8 + j;
                float4 cv = __ldg((const float4*)(cc + (size_t)cl * N_FEAT) + lane);
                float d = xv.x * cv.x + xv.y * cv.y + xv.z * cv.z + xv.w * cv.w;
#pragma unroll
                for (int o = 16; o >= 1; o >>= 1)
                    d += __shfl_xor_sync(0xFFFFFFFFu, d, o);
                if (lane == 0) {
                    float s = d - 0.5f * s2;
                    bestk[cl] = ((unsigned long long)orderf(s) << 32) |
                                (unsigned long long)(0xFFFFFFFFu - (uint32_t)token);
                }
            }
        } else if (lane < 8) {
            bestk[wid * 8 + lane] = 0ull;
        }
    }
    __syncthreads();

    // ldmatrix geometry
    const int lr = (lane & 7) | (lane & 8);    // row-within-16
    const int lk = lane & 16;                  // 16B column select
    const uint32_t sw = (uint32_t)((lr & 7) << 4);
    const int nb = nh * 32;

    uint32_t aAh[2], aB[2];
#pragma unroll
    for (int mi = 0; mi < 2; ++mi)
        aAh[mi] = sb + OFF_XHI + (uint32_t)((mg * 32 + mi * 16 + lr) * 256);
#pragma unroll
    for (int np = 0; np < 2; ++np)
        aB[np] = sb + OFF_BHI + (uint32_t)((nb + np * 16 + lr) * 256);

    for (int t = bid; t < NT; t += GRID_MAIN) {
        const int base = t * TILE_M;

        // ---- convert: v regs -> bf16-hi XHI + |x|^2 ----
        {
            float s = 0.f;
#pragma unroll
            for (int j = 0; j < 8; ++j) {
                float4 a = v[2 * j], b = v[2 * j + 1];
                uint32_t h0 = cvt_bf2(a.y, a.x), h1 = cvt_bf2(a.w, a.z);
                uint32_t h2 = cvt_bf2(b.y, b.x), h3 = cvt_bf2(b.w, b.z);
                s += a.x * a.x + a.y * a.y + a.z * a.z + a.w * a.w;
                s += b.x * b.x + b.y * b.y + b.z * b.z + b.w * b.w;
                uint32_t off = (uint32_t)(crow * 256 + (((chalf * 8 + j) * 16) ^ ((crow & 7) << 4)));
                sts128(sb + OFF_XHI + off, h0, h1, h2, h3);
            }
            s += __shfl_xor_sync(0xFFFFFFFFu, s, 1);
            if (chalf == 0) x2s[crow] = s;
        }

        // issue next tile's LDGs now (v dead; hidden behind MMA+epilogue)
        LOADV(t + GRID_MAIN);

        __syncthreads();      // (1) XHI + x2s ready

        // ---- MMA: hh term ----
        float c[2][4][4];
#pragma unroll
        for (int mi = 0; mi < 2; ++mi)
#pragma unroll
            for (int ni = 0; ni < 4; ++ni)
#pragma unroll
                for (int r = 0; r < 4; ++r) c[mi][ni][r] = 0.f;

#pragma unroll
        for (int ks = 0; ks < 8; ++ks) {
            const uint32_t ko = ((uint32_t)(ks * 32 + lk)) ^ sw;
            uint32_t ah[2][4];
#pragma unroll
            for (int mi = 0; mi < 2; ++mi)
                ldm4(ah[mi][0], ah[mi][1], ah[mi][2], ah[mi][3], aAh[mi] + ko);
            uint32_t bf[4][2];
#pragma unroll
            for (int np = 0; np < 2; ++np) {
                uint32_t r0, r1, r2, r3;
                ldm4(r0, r1, r2, r3, aB[np] + ko);
                bf[np * 2][0] = r0;  bf[np * 2 + 1][0] = r1;
                bf[np * 2][1] = r2;  bf[np * 2 + 1][1] = r3;
            }
#pragma unroll
            for (int mi = 0; mi < 2; ++mi)
#pragma unroll
                for (int ni = 0; ni < 4; ++ni)
                    mma16816(c[mi][ni][0], c[mi][ni][1], c[mi][ni][2], c[mi][ni][3],
                             ah[mi][0], ah[mi][1], ah[mi][2], ah[mi][3],
                             bf[ni][0], bf[ni][1]);
        }

        // ---- epilogue: scores, threshold vs exact best, rescue ----
        float h2v[2][2];
        bool vld[2][2];
#pragma unroll
        for (int mi = 0; mi < 2; ++mi)
#pragma unroll
            for (int p = 0; p < 2; ++p) {
                int row = mg * 32 + mi * 16 + (lane >> 2) + p * 8;
                h2v[mi][p] = 0.5f * x2s[row];
                vld[mi][p] = (base + row) < n_tokens;
            }

#pragma unroll
        for (int mi = 0; mi < 2; ++mi)
#pragma unroll
            for (int ni = 0; ni < 4; ++ni)
#pragma unroll
                for (int p = 0; p < 2; ++p)
#pragma unroll
                    for (int ci = 0; ci < 2; ++ci) {
                        float sc = c[mi][ni][ci + 2 * p] - h2v[mi][p];
                        c[mi][ni][ci + 2 * p] = vld[mi][p] ? sc : NEGINF;
                    }

        float thrf[4][2];
#pragma unroll
        for (int ni = 0; ni < 4; ++ni)
#pragma unroll
            for (int ci = 0; ci < 2; ++ci) {
                int cl = nb + ni * 8 + (lane & 3) * 2 + ci;
                uint32_t hi = lds32v(sb + (uint32_t)(OFF_BEST + cl * 8 + 4));
                thrf[ni][ci] = inv_orderf(hi) - EPS;    // seeded => finite
            }

        uint32_t myMask = 0;
#pragma unroll
        for (int ni = 0; ni < 4; ++ni)
#pragma unroll
            for (int ci = 0; ci < 2; ++ci)
#pragma unroll
                for (int p = 0; p < 2; ++p)
#pragma unroll
                    for (int mi = 0; mi < 2; ++mi)
                        if (c[mi][ni][ci + 2 * p] >= thrf[ni][ci])
                            myMask |= 1u << ((ni << 3) | (ci << 2) | (p << 1) | mi);

        uint32_t active = __ballot_sync(0xFFFFFFFFu, myMask != 0);
        while (active) {
            int src = __ffs(active) - 1;
            active &= active - 1;
            uint32_t m = __shfl_sync(0xFFFFFFFFu, myMask, src);
            while (m) {
                int b = __ffs(m) - 1;
                m &= m - 1;
                int mi = b & 1, p = (b >> 1) & 1, ci = (b >> 2) & 1, ni = b >> 3;
                int row = mg * 32 + mi * 16 + (src >> 2) + p * 8;
                int cl  = nb + ni * 8 + (src & 3) * 2 + ci;
                warp_rescore(x, sb, base + row, cl, x2s[row], lane, bestk);
            }
        }

        __syncthreads();      // (2) all XHI/x2s reads done before next convert
    }

    if (tid < N_CLUS)
        g_part[(size_t)bid * N_CLUS + tid] = bestk[tid];
}

// ---------------- gather: reduce partials, copy winning rows ----------------
__global__ void gather_k(const float* __restrict__ x, float* __restrict__ out) {
    __shared__ unsigned long long red[256];
    const int c = blockIdx.x, tid = threadIdx.x;
    unsigned long long v = 0ull;
    if (tid < GRID_MAIN) v = g_part[(size_t)tid * N_CLUS + c];
    red[tid] = v;
    __syncthreads();
#pragma unroll
    for (int s = 128; s > 0; s >>= 1) {
        if (tid < s) { unsigned long long o = red[tid + s]; if (o > red[tid]) red[tid] = o; }
        __syncthreads();
    }
    unsigned int gi = 0xFFFFFFFFu - (unsigned int)(red[0] & 0xFFFFFFFFull);
    if (tid < N_FEAT)
        out[c * N_FEAT + tid] = x[(size_t)gi * N_FEAT + tid];
}

// ---------------- launch ----------------
extern "C" void kernel_launch(void* const* d_in, const int* in_sizes, int n_in,
                              void* d_out, int out_size)
{
    const float* x  = (const float*)d_in[0];
    const float* cc = (const float*)d_in[1];
    int n_tokens = in_sizes[0] / N_FEAT;

    cudaFuncSetAttribute(cluster_hmma, cudaFuncAttributeMaxDynamicSharedMemorySize, SMEM_TOTAL);
    cluster_hmma<<<GRID_MAIN, THREADS, SMEM_TOTAL>>>(x, cc, n_tokens);
    gather_k<<<N_CLUS, 256>>>(x, (float*)d_out);
}

// round 9
// speedup vs baseline: 3.4495x; 2.2509x over previous
#include <cuda_runtime.h>
#include <cuda_bf16.h>
#include <cstdint>

#define N_FEAT    128
#define N_CLUS    64
#define TILE_M    128
#define THREADS   256
#define GRID_MAIN 148
#define EPS       1.0f
#define TWOEPS    2.0f
#define NEGINF    (-3.4e38f)

// smem layout (bytes)
#define OFF_STAGE 0          // 4 slots * 32768B (64 rows * 512B fp32, swizzled)
#define OFF_XHI   131072     // 128 rows * 256B bf16 (hi), swizzled
#define OFF_BHI   163840     // 64 rows * 256B bf16 (hi), swizzled
#define OFF_CCF   180224     // 64 * 128 fp32 centers, linear
#define OFF_X2    212992     // 128 floats
#define OFF_BEST  213504     // 64 u64 exact keys
#define SMEM_TOTAL 214016

__device__ unsigned long long g_part[GRID_MAIN * N_CLUS];

// ---------------- helpers ----------------
__device__ __forceinline__ uint32_t smem_u32(const void* p) {
    return (uint32_t)__cvta_generic_to_shared(p);
}
__device__ __forceinline__ uint32_t cvt_bf2(float hi, float lo) {
    uint32_t d;
    asm("cvt.rn.bf16x2.f32 %0, %1, %2;" : "=r"(d) : "f"(hi), "f"(lo)); // low half = lo
    return d;
}
__device__ __forceinline__ uint32_t orderf(float f) {
    uint32_t u = __float_as_uint(f);
    return u ^ (((uint32_t)((int32_t)u >> 31)) | 0x80000000u);
}
__device__ __forceinline__ float inv_orderf(uint32_t k) {
    uint32_t u = (k & 0x80000000u) ? (k ^ 0x80000000u) : ~k;
    return __uint_as_float(u);   // k==0 -> NaN; fmaxf(NaN,x)=x handles bootstrap
}
__device__ __forceinline__ void sts128(uint32_t a, uint32_t x, uint32_t y, uint32_t z, uint32_t w) {
    asm volatile("st.shared.v4.b32 [%0], {%1,%2,%3,%4};" :: "r"(a), "r"(x), "r"(y), "r"(z), "r"(w) : "memory");
}
__device__ __forceinline__ void lds128(float& x, float& y, float& z, float& w, uint32_t a) {
    asm volatile("ld.shared.v4.f32 {%0,%1,%2,%3}, [%4];"
                 : "=f"(x), "=f"(y), "=f"(z), "=f"(w) : "r"(a));
}
__device__ __forceinline__ uint32_t lds32v(uint32_t a) {
    uint32_t d;
    asm volatile("ld.volatile.shared.b32 %0, [%1];" : "=r"(d) : "r"(a));
    return d;
}
__device__ __forceinline__ void ldm4(uint32_t& r0, uint32_t& r1, uint32_t& r2, uint32_t& r3, uint32_t a) {
    asm volatile("ldmatrix.sync.aligned.m8n8.x4.shared.b16 {%0,%1,%2,%3}, [%4];"
                 : "=r"(r0), "=r"(r1), "=r"(r2), "=r"(r3) : "r"(a));
}
__device__ __forceinline__ void mma16816(float& c0, float& c1, float& c2, float& c3,
                                         uint32_t a0, uint32_t a1, uint32_t a2, uint32_t a3,
                                         uint32_t b0, uint32_t b1) {
    asm volatile("mma.sync.aligned.m16n8k16.row.col.f32.bf16.bf16.f32 "
                 "{%0,%1,%2,%3},{%4,%5,%6,%7},{%8,%9},{%0,%1,%2,%3};"
                 : "+f"(c0), "+f"(c1), "+f"(c2), "+f"(c3)
                 : "r"(a0), "r"(a1), "r"(a2), "r"(a3), "r"(b0), "r"(b1));
}
__device__ __forceinline__ void cp16(uint32_t s, const void* g) {
    asm volatile("cp.async.cg.shared.global [%0], [%1], 16;" :: "r"(s), "l"(g));
}
__device__ __forceinline__ void cp_commit() { asm volatile("cp.async.commit_group;"); }
__device__ __forceinline__ void cp_wait2()  { asm volatile("cp.async.wait_group 2;" ::: "memory"); }

extern __shared__ char smem[];

// prefetch one 64-row half tile (half=0/1) of tile t into ring slot; one commit group
__device__ __forceinline__ void prefetch_half(const float* __restrict__ x, int t, int NT,
                                              int n_tokens, int slot, int half,
                                              int tid, uint32_t sb) {
    if (t < NT) {
        const int base = t * TILE_M + half * 64;
#pragma unroll
        for (int c = 0; c < 8; ++c) {
            int chunk = tid + c * THREADS;      // 0..2047
            int r = chunk >> 5, q = chunk & 31; // row 0..63, 16B chunk
            if (base + r < n_tokens)
                cp16(sb + (uint32_t)(OFF_STAGE + slot * 32768 + r * 512 + ((q ^ (r & 31)) << 4)),
                     x + (size_t)(base + r) * N_FEAT + q * 4);
        }
    }
    cp_commit();
}

// exact warp-cooperative rescore of (row in tile, cluster) from stage smem + CCF
__device__ __forceinline__ void warp_rescore(uint32_t sb, int slotbase, int row, int cl, int base,
                                             int lane, const float* x2s,
                                             unsigned long long* bestk) {
    const int sl = slotbase + (row >> 6);     // slotbase even; +1 stays in ring
    const int r  = row & 63;
    float4 xv, cv;
    lds128(xv.x, xv.y, xv.z, xv.w,
           sb + (uint32_t)(OFF_STAGE + sl * 32768 + r * 512 + (((lane ^ (r & 31)) & 31) << 4)));
    lds128(cv.x, cv.y, cv.z, cv.w,
           sb + (uint32_t)(OFF_CCF + cl * 512 + (lane << 4)));
    float d = xv.x * cv.x + xv.y * cv.y + xv.z * cv.z + xv.w * cv.w;
#pragma unroll
    for (int o = 16; o >= 1; o >>= 1)
        d += __shfl_xor_sync(0xFFFFFFFFu, d, o);
    if (lane == 0) {
        float s = d - 0.5f * x2s[row];
        unsigned long long key =
            ((unsigned long long)orderf(s) << 32) |
            (unsigned long long)(0xFFFFFFFFu - (uint32_t)(base + row));
        atomicMax(&bestk[cl], key);
    }
}

__global__ void __launch_bounds__(THREADS, 1)
cluster_hmma(const float* __restrict__ x, const float* __restrict__ cc, int n_tokens)
{
    const int tid  = threadIdx.x;
    const int lane = tid & 31;
    const int wid  = tid >> 5;
    const int mg   = wid >> 1;     // m-group: rows [mg*32, mg*32+32)
    const int nh   = wid & 1;      // n-half:  cols [nh*32, nh*32+32)
    const int bid  = blockIdx.x;
    const uint32_t sb = smem_u32(smem);
    const int NT = (n_tokens + TILE_M - 1) / TILE_M;

    const int crow = tid >> 1, chalf = tid & 1;   // convert mapping: 2 threads/row

    // depth-2 prologue: tile bid -> slots 0,1 ; tile bid+G -> slots 2,3
    prefetch_half(x, bid,             NT, n_tokens, 0, 0, tid, sb);
    prefetch_half(x, bid,             NT, n_tokens, 1, 1, tid, sb);
    prefetch_half(x, bid + GRID_MAIN, NT, n_tokens, 2, 0, tid, sb);
    prefetch_half(x, bid + GRID_MAIN, NT, n_tokens, 3, 1, tid, sb);

    // ---- centers: fp32 copy (linear) + bf16-hi swizzled ----
    {
        const float4* c4 = (const float4*)cc;
        float4* f4 = (float4*)(smem + OFF_CCF);
        for (int i = tid; i < N_CLUS * N_FEAT / 4; i += THREADS)
            f4[i] = c4[i];
    }
#pragma unroll
    for (int i = tid; i < N_CLUS * 16; i += THREADS) {   // 16 chunks of 8 per row
        int n = i >> 4, kc = i & 15;
        const float4* cp = (const float4*)(cc + n * N_FEAT + kc * 8);
        float4 ca = cp[0], cb = cp[1];
        uint32_t h0 = cvt_bf2(ca.y, ca.x), h1 = cvt_bf2(ca.w, ca.z);
        uint32_t h2 = cvt_bf2(cb.y, cb.x), h3 = cvt_bf2(cb.w, cb.z);
        uint32_t off = (uint32_t)(n * 256 + ((kc * 16) ^ ((n & 7) << 4)));
        sts128(sb + OFF_BHI + off, h0, h1, h2, h3);
    }
    if (tid < N_CLUS) ((unsigned long long*)(smem + OFF_BEST))[tid] = 0ull;
    __syncthreads();

    // ---- preload Bhi fragments into registers (constant across all tiles) ----
    const int lr = (lane & 7) | (lane & 8);    // ldmatrix row-within-16
    const int lk = lane & 16;                  // 16B column select
    const uint32_t sw = (uint32_t)((lr & 7) << 4);
    const int nb = nh * 32;

    uint32_t bhi[8][4][2];
#pragma unroll
    for (int ks = 0; ks < 8; ++ks) {
#pragma unroll
        for (int np = 0; np < 2; ++np) {
            uint32_t addr = sb + OFF_BHI + (uint32_t)((nb + np * 16 + lr) * 256)
                          + (((uint32_t)(ks * 32 + lk)) ^ sw);
            uint32_t r0, r1, r2, r3;
            ldm4(r0, r1, r2, r3, addr);
            bhi[ks][np * 2][0] = r0;  bhi[ks][np * 2 + 1][0] = r1;
            bhi[ks][np * 2][1] = r2;  bhi[ks][np * 2 + 1][1] = r3;
        }
    }

    uint32_t aAh[2];
#pragma unroll
    for (int mi = 0; mi < 2; ++mi)
        aAh[mi] = sb + OFF_XHI + (uint32_t)((mg * 32 + mi * 16 + lr) * 256);

    float* x2s = (float*)(smem + OFF_X2);
    unsigned long long* bestk = (unsigned long long*)(smem + OFF_BEST);

    int it = 0;
    for (int t = bid; t < NT; t += GRID_MAIN, ++it) {
        const int base = t * TILE_M;
        const int slotbase = (2 * it) & 3;    // this tile's slots: slotbase, slotbase+1

        cp_wait2();           // this tile's 2 groups (oldest) have landed
        __syncthreads();      // (a) stage visible CTA-wide

        // ---- convert: stage fp32 -> bf16-hi XHI + |x|^2 ----
        {
            const bool val = (base + crow) < n_tokens;
            const int sl = slotbase + (crow >> 6);
            const int r  = crow & 63;
            const uint32_t rowb = sb + (uint32_t)(OFF_STAGE + sl * 32768 + r * 512);
            const int rsw = r & 31;
            float s = 0.f;
#pragma unroll
            for (int j = 0; j < 8; ++j) {
                float4 a, b;
                lds128(a.x, a.y, a.z, a.w, rowb + (uint32_t)(((chalf * 16 + 2 * j) ^ rsw) << 4));
                lds128(b.x, b.y, b.z, b.w, rowb + (uint32_t)(((chalf * 16 + 2 * j + 1) ^ rsw) << 4));
                if (!val) { a = make_float4(0.f, 0.f, 0.f, 0.f); b = a; }
                uint32_t h0 = cvt_bf2(a.y, a.x), h1 = cvt_bf2(a.w, a.z);
                uint32_t h2 = cvt_bf2(b.y, b.x), h3 = cvt_bf2(b.w, b.z);
                s += a.x * a.x + a.y * a.y + a.z * a.z + a.w * a.w;
                s += b.x * b.x + b.y * b.y + b.z * b.z + b.w * b.w;
                uint32_t off = (uint32_t)(crow * 256 + (((chalf * 8 + j) * 16) ^ ((crow & 7) << 4)));
                sts128(sb + OFF_XHI + off, h0, h1, h2, h3);
            }
            s += __shfl_xor_sync(0xFFFFFFFFu, s, 1);
            if (chalf == 0) x2s[crow] = s;
        }
        __syncthreads();      // (b) XHI + x2s ready

        // ---- MMA: hh term only ----
        float c[2][4][4];
#pragma unroll
        for (int mi = 0; mi < 2; ++mi)
#pragma unroll
            for (int ni = 0; ni < 4; ++ni)
#pragma unroll
                for (int r = 0; r < 4; ++r) c[mi][ni][r] = 0.f;

#pragma unroll
        for (int ks = 0; ks < 8; ++ks) {
            const uint32_t ko = ((uint32_t)(ks * 32 + lk)) ^ sw;
            uint32_t ah[2][4];
#pragma unroll
            for (int mi = 0; mi < 2; ++mi)
                ldm4(ah[mi][0], ah[mi][1], ah[mi][2], ah[mi][3], aAh[mi] + ko);
#pragma unroll
            for (int mi = 0; mi < 2; ++mi)
#pragma unroll
                for (int ni = 0; ni < 4; ++ni)
                    mma16816(c[mi][ni][0], c[mi][ni][1], c[mi][ni][2], c[mi][ni][3],
                             ah[mi][0], ah[mi][1], ah[mi][2], ah[mi][3],
                             bhi[ks][ni][0], bhi[ks][ni][1]);
        }

        // ---- epilogue (R5-exact): scores, per-warp max, threshold, rescue ----
        float h2v[2][2];
        bool vld[2][2];
#pragma unroll
        for (int mi = 0; mi < 2; ++mi)
#pragma unroll
            for (int p = 0; p < 2; ++p) {
                int row = mg * 32 + mi * 16 + (lane >> 2) + p * 8;
                h2v[mi][p] = 0.5f * x2s[row];
                vld[mi][p] = (base + row) < n_tokens;
            }

#pragma unroll
        for (int mi = 0; mi < 2; ++mi)
#pragma unroll
            for (int ni = 0; ni < 4; ++ni)
#pragma unroll
                for (int p = 0; p < 2; ++p)
#pragma unroll
                    for (int ci = 0; ci < 2; ++ci) {
                        float sc = c[mi][ni][ci + 2 * p] - h2v[mi][p];
                        c[mi][ni][ci + 2 * p] = vld[mi][p] ? sc : NEGINF;
                    }

        float mloc[4][2];
#pragma unroll
        for (int ni = 0; ni < 4; ++ni)
#pragma unroll
            for (int ci = 0; ci < 2; ++ci) {
                float m = fmaxf(fmaxf(c[0][ni][ci], c[0][ni][ci + 2]),
                                fmaxf(c[1][ni][ci], c[1][ni][ci + 2]));
#pragma unroll
                for (int d = 4; d <= 16; d <<= 1)
                    m = fmaxf(m, __shfl_xor_sync(0xFFFFFFFFu, m, d));
                mloc[ni][ci] = m;
            }

        float thrf[4][2];
#pragma unroll
        for (int ni = 0; ni < 4; ++ni)
#pragma unroll
            for (int ci = 0; ci < 2; ++ci) {
                int cl = nb + ni * 8 + (lane & 3) * 2 + ci;
                uint32_t hi = lds32v(sb + (uint32_t)(OFF_BEST + cl * 8 + 4));
                float b = inv_orderf(hi);                        // NaN if unset
                thrf[ni][ci] = fmaxf(b - EPS, mloc[ni][ci] - TWOEPS);
            }

        uint32_t myMask = 0;
#pragma unroll
        for (int ni = 0; ni < 4; ++ni)
#pragma unroll
            for (int ci = 0; ci < 2; ++ci)
#pragma unroll
                for (int p = 0; p < 2; ++p)
#pragma unroll
                    for (int mi = 0; mi < 2; ++mi)
                        if (c[mi][ni][ci + 2 * p] >= thrf[ni][ci])
                            myMask |= 1u << ((ni << 3) | (ci << 2) | (p << 1) | mi);

        uint32_t active = __ballot_sync(0xFFFFFFFFu, myMask != 0);
        while (active) {
            int src = __ffs(active) - 1;
            active &= active - 1;
            uint32_t m = __shfl_sync(0xFFFFFFFFu, myMask, src);
            while (m) {
                int b = __ffs(m) - 1;
                m &= m - 1;
                int mi = b & 1, p = (b >> 1) & 1, ci = (b >> 2) & 1, ni = b >> 3;
                int row = mg * 32 + mi * 16 + (src >> 2) + p * 8;
                int cl  = nb + ni * 8 + (src & 3) * 2 + ci;
                warp_rescore(sb, slotbase, row, cl, base, lane, x2s, bestk);
            }
        }
        __syncthreads();      // (c) all stage/XHI/x2s reads done before refill

        // refill the slots this tile just freed with tile t+2G (consumed at iter it+2)
        prefetch_half(x, t + 2 * GRID_MAIN, NT, n_tokens, slotbase,     0, tid, sb);
        prefetch_half(x, t + 2 * GRID_MAIN, NT, n_tokens, slotbase + 1, 1, tid, sb);
    }

    __syncthreads();
    if (tid < N_CLUS)
        g_part[(size_t)bid * N_CLUS + tid] = bestk[tid];
}

// ---------------- gather: reduce partials, copy winning rows ----------------
__global__ void gather_k(const float* __restrict__ x, float* __restrict__ out) {
    __shared__ unsigned long long red[256];
    const int c = blockIdx.x, tid = threadIdx.x;
    unsigned long long v = 0ull;
    if (tid < GRID_MAIN) v = g_part[(size_t)tid * N_CLUS + c];
    red[tid] = v;
    __syncthreads();
#pragma unroll
    for (int s = 128; s > 0; s >>= 1) {
        if (tid < s) { unsigned long long o = red[tid + s]; if (o > red[tid]) red[tid] = o; }
        __syncthreads();
    }
    unsigned int gi = 0xFFFFFFFFu - (unsigned int)(red[0] & 0xFFFFFFFFull);
    if (tid < N_FEAT)
        out[c * N_FEAT + tid] = x[(size_t)gi * N_FEAT + tid];
}

// ---------------- launch ----------------
extern "C" void kernel_launch(void* const* d_in, const int* in_sizes, int n_in,
                              void* d_out, int out_size)
{
    const float* x  = (const float*)d_in[0];
    const float* cc = (const float*)d_in[1];
    int n_tokens = in_sizes[0] / N_FEAT;

    cudaFuncSetAttribute(cluster_hmma, cudaFuncAttributeMaxDynamicSharedMemorySize, SMEM_TOTAL);
    cluster_hmma<<<GRID_MAIN, THREADS, SMEM_TOTAL>>>(x, cc, n_tokens);
    gather_k<<<N_CLUS, 256>>>(x, (float*)d_out);
}

// round 10
// speedup vs baseline: 3.6598x; 1.0610x over previous
#include <cuda_runtime.h>
#include <cuda_bf16.h>
#include <cstdint>

#define N_FEAT    128
#define N_CLUS    64
#define TILE_M    64
#define THREADS   128
#define GRID_MAIN 296
#define EPS       1.0f
#define TWOEPS    2.0f
#define NEGINF    (-3.4e38f)

// smem layout (bytes)
#define OFF_STAGE 0          // 2 bufs * 32768B (64 rows * 512B fp32, swizzled)
#define OFF_XHI   65536      // 64 rows * 256B bf16 (hi), swizzled
#define OFF_BHI   81920      // 64 rows * 256B bf16 (hi), swizzled
#define OFF_X2    98304      // 64 floats
#define OFF_BEST  98560      // 64 u64 exact keys
#define SMEM_TOTAL 99072

__device__ unsigned long long g_part[GRID_MAIN * N_CLUS];

// ---------------- helpers ----------------
__device__ __forceinline__ uint32_t smem_u32(const void* p) {
    return (uint32_t)__cvta_generic_to_shared(p);
}
__device__ __forceinline__ uint32_t cvt_bf2(float hi, float lo) {
    uint32_t d;
    asm("cvt.rn.bf16x2.f32 %0, %1, %2;" : "=r"(d) : "f"(hi), "f"(lo)); // low half = lo
    return d;
}
__device__ __forceinline__ uint32_t orderf(float f) {
    uint32_t u = __float_as_uint(f);
    return u ^ (((uint32_t)((int32_t)u >> 31)) | 0x80000000u);
}
__device__ __forceinline__ float inv_orderf(uint32_t k) {
    uint32_t u = (k & 0x80000000u) ? (k ^ 0x80000000u) : ~k;
    return __uint_as_float(u);   // k==0 -> NaN; fmaxf(NaN,x)=x handles bootstrap
}
__device__ __forceinline__ void sts128(uint32_t a, uint32_t x, uint32_t y, uint32_t z, uint32_t w) {
    asm volatile("st.shared.v4.b32 [%0], {%1,%2,%3,%4};" :: "r"(a), "r"(x), "r"(y), "r"(z), "r"(w) : "memory");
}
__device__ __forceinline__ void lds128(float& x, float& y, float& z, float& w, uint32_t a) {
    asm volatile("ld.shared.v4.f32 {%0,%1,%2,%3}, [%4];"
                 : "=f"(x), "=f"(y), "=f"(z), "=f"(w) : "r"(a));
}
__device__ __forceinline__ uint32_t lds32v(uint32_t a) {
    uint32_t d;
    asm volatile("ld.volatile.shared.b32 %0, [%1];" : "=r"(d) : "r"(a));
    return d;
}
__device__ __forceinline__ void ldm4(uint32_t& r0, uint32_t& r1, uint32_t& r2, uint32_t& r3, uint32_t a) {
    asm volatile("ldmatrix.sync.aligned.m8n8.x4.shared.b16 {%0,%1,%2,%3}, [%4];"
                 : "=r"(r0), "=r"(r1), "=r"(r2), "=r"(r3) : "r"(a));
}
__device__ __forceinline__ void mma16816(float& c0, float& c1, float& c2, float& c3,
                                         uint32_t a0, uint32_t a1, uint32_t a2, uint32_t a3,
                                         uint32_t b0, uint32_t b1) {
    asm volatile("mma.sync.aligned.m16n8k16.row.col.f32.bf16.bf16.f32 "
                 "{%0,%1,%2,%3},{%4,%5,%6,%7},{%8,%9},{%0,%1,%2,%3};"
                 : "+f"(c0), "+f"(c1), "+f"(c2), "+f"(c3)
                 : "r"(a0), "r"(a1), "r"(a2), "r"(a3), "r"(b0), "r"(b1));
}
__device__ __forceinline__ void cp16(uint32_t s, const void* g) {
    asm volatile("cp.async.cg.shared.global [%0], [%1], 16;" :: "r"(s), "l"(g));
}
__device__ __forceinline__ void cp_commit() { asm volatile("cp.async.commit_group;"); }
__device__ __forceinline__ void cp_wait1()  { asm volatile("cp.async.wait_group 1;" ::: "memory"); }

extern __shared__ char smem[];

// prefetch one 64-row tile into stage buffer b via cp.async (one commit group)
__device__ __forceinline__ void prefetch(const float* __restrict__ x, int t, int NT,
                                         int n_tokens, int b, int tid, uint32_t sb) {
    if (t < NT) {
        const int base = t * TILE_M;
#pragma unroll
        for (int c = 0; c < 16; ++c) {
            int chunk = tid + c * THREADS;      // 0..2047
            int r = chunk >> 5, q = chunk & 31; // row 0..63, 16B chunk
            if (base + r < n_tokens)
                cp16(sb + (uint32_t)(OFF_STAGE + b * 32768 + r * 512 + ((q ^ (r & 31)) << 4)),
                     x + (size_t)(base + r) * N_FEAT + q * 4);
        }
    }
    cp_commit();
}

// exact warp-cooperative rescore: x row from stage smem, center from GLOBAL (L2-hot; rare)
__device__ __forceinline__ void warp_rescore(uint32_t sb, const float* __restrict__ cc,
                                             int buf, int row, int cl, int base,
                                             int lane, const float* x2s,
                                             unsigned long long* bestk) {
    float4 xv;
    lds128(xv.x, xv.y, xv.z, xv.w,
           sb + (uint32_t)(OFF_STAGE + buf * 32768 + row * 512 + (((lane ^ (row & 31)) & 31) << 4)));
    float4 cv = __ldg((const float4*)(cc + (size_t)cl * N_FEAT) + lane);
    float d = xv.x * cv.x + xv.y * cv.y + xv.z * cv.z + xv.w * cv.w;
#pragma unroll
    for (int o = 16; o >= 1; o >>= 1)
        d += __shfl_xor_sync(0xFFFFFFFFu, d, o);
    if (lane == 0) {
        float s = d - 0.5f * x2s[row];
        unsigned long long key =
            ((unsigned long long)orderf(s) << 32) |
            (unsigned long long)(0xFFFFFFFFu - (uint32_t)(base + row));
        atomicMax(&bestk[cl], key);
    }
}

__global__ void __launch_bounds__(THREADS, 2)
cluster_hmma(const float* __restrict__ x, const float* __restrict__ cc, int n_tokens)
{
    const int tid  = threadIdx.x;
    const int lane = tid & 31;
    const int wid  = tid >> 5;     // 0..3
    const int mg   = wid >> 1;     // m-group: rows [mg*32, mg*32+32)
    const int nh   = wid & 1;      // n-half:  cols [nh*32, nh*32+32)
    const int bid  = blockIdx.x;
    const uint32_t sb = smem_u32(smem);
    const int NT = (n_tokens + TILE_M - 1) / TILE_M;

    const int crow = tid >> 1, chalf = tid & 1;   // convert mapping: 2 threads/row

    // prologue: tile bid -> stage[0]
    prefetch(x, bid, NT, n_tokens, 0, tid, sb);

    // ---- centers bf16-hi swizzled in smem ----
#pragma unroll
    for (int i = tid; i < N_CLUS * 16; i += THREADS) {   // 16 chunks of 8 per row
        int n = i >> 4, kc = i & 15;
        const float4* cp = (const float4*)(cc + n * N_FEAT + kc * 8);
        float4 ca = cp[0], cb = cp[1];
        uint32_t h0 = cvt_bf2(ca.y, ca.x), h1 = cvt_bf2(ca.w, ca.z);
        uint32_t h2 = cvt_bf2(cb.y, cb.x), h3 = cvt_bf2(cb.w, cb.z);
        uint32_t off = (uint32_t)(n * 256 + ((kc * 16) ^ ((n & 7) << 4)));
        sts128(sb + OFF_BHI + off, h0, h1, h2, h3);
    }
    if (tid < N_CLUS) ((unsigned long long*)(smem + OFF_BEST))[tid] = 0ull;
    __syncthreads();

    // ---- preload Bhi fragments into registers (constant across all tiles) ----
    const int lr = (lane & 7) | (lane & 8);    // ldmatrix row-within-16
    const int lk = lane & 16;                  // 16B column select
    const uint32_t sw = (uint32_t)((lr & 7) << 4);
    const int nb = nh * 32;

    uint32_t bhi[8][4][2];
#pragma unroll
    for (int ks = 0; ks < 8; ++ks) {
#pragma unroll
        for (int np = 0; np < 2; ++np) {
            uint32_t addr = sb + OFF_BHI + (uint32_t)((nb + np * 16 + lr) * 256)
                          + (((uint32_t)(ks * 32 + lk)) ^ sw);
            uint32_t r0, r1, r2, r3;
            ldm4(r0, r1, r2, r3, addr);
            bhi[ks][np * 2][0] = r0;  bhi[ks][np * 2 + 1][0] = r1;
            bhi[ks][np * 2][1] = r2;  bhi[ks][np * 2 + 1][1] = r3;
        }
    }

    uint32_t aAh[2];
#pragma unroll
    for (int mi = 0; mi < 2; ++mi)
        aAh[mi] = sb + OFF_XHI + (uint32_t)((mg * 32 + mi * 16 + lr) * 256);

    float* x2s = (float*)(smem + OFF_X2);
    unsigned long long* bestk = (unsigned long long*)(smem + OFF_BEST);

    int it = 0;
    for (int t = bid; t < NT; t += GRID_MAIN, ++it) {
        const int base = t * TILE_M;
        const int buf  = it & 1;

        cp_wait1();           // stage[buf] landed (the older of <=2 groups)
        __syncthreads();      // (a) visible CTA-wide; stage[buf^1] reads (prev rescore) done

        // ---- convert: stage fp32 -> bf16-hi XHI + |x|^2 ----
        {
            const bool val = (base + crow) < n_tokens;
            const uint32_t rowb = sb + (uint32_t)(OFF_STAGE + buf * 32768 + crow * 512);
            const int rsw = crow & 31;
            float s = 0.f;
#pragma unroll
            for (int j = 0; j < 8; ++j) {
                float4 a, b;
                lds128(a.x, a.y, a.z, a.w, rowb + (uint32_t)(((chalf * 16 + 2 * j) ^ rsw) << 4));
                lds128(b.x, b.y, b.z, b.w, rowb + (uint32_t)(((chalf * 16 + 2 * j + 1) ^ rsw) << 4));
                if (!val) { a = make_float4(0.f, 0.f, 0.f, 0.f); b = a; }
                uint32_t h0 = cvt_bf2(a.y, a.x), h1 = cvt_bf2(a.w, a.z);
                uint32_t h2 = cvt_bf2(b.y, b.x), h3 = cvt_bf2(b.w, b.z);
                s += a.x * a.x + a.y * a.y + a.z * a.z + a.w * a.w;
                s += b.x * b.x + b.y * b.y + b.z * b.z + b.w * b.w;
                uint32_t off = (uint32_t)(crow * 256 + (((chalf * 8 + j) * 16) ^ ((crow & 7) << 4)));
                sts128(sb + OFF_XHI + off, h0, h1, h2, h3);
            }
            s += __shfl_xor_sync(0xFFFFFFFFu, s, 1);
            if (chalf == 0) x2s[crow] = s;
        }

        // issue next tile's cp.async into the other buffer (reads of it finished last iter)
        prefetch(x, t + GRID_MAIN, NT, n_tokens, buf ^ 1, tid, sb);

        __syncthreads();      // (b) XHI + x2s ready

        // ---- MMA: hh term only ----
        float c[2][4][4];
#pragma unroll
        for (int mi = 0; mi < 2; ++mi)
#pragma unroll
            for (int ni = 0; ni < 4; ++ni)
#pragma unroll
                for (int r = 0; r < 4; ++r) c[mi][ni][r] = 0.f;

#pragma unroll
        for (int ks = 0; ks < 8; ++ks) {
            const uint32_t ko = ((uint32_t)(ks * 32 + lk)) ^ sw;
            uint32_t ah[2][4];
#pragma unroll
            for (int mi = 0; mi < 2; ++mi)
                ldm4(ah[mi][0], ah[mi][1], ah[mi][2], ah[mi][3], aAh[mi] + ko);
#pragma unroll
            for (int mi = 0; mi < 2; ++mi)
#pragma unroll
                for (int ni = 0; ni < 4; ++ni)
                    mma16816(c[mi][ni][0], c[mi][ni][1], c[mi][ni][2], c[mi][ni][3],
                             ah[mi][0], ah[mi][1], ah[mi][2], ah[mi][3],
                             bhi[ks][ni][0], bhi[ks][ni][1]);
        }

        // ---- epilogue: scores, per-warp max, threshold, rescue ----
        float h2v[2][2];
        bool vld[2][2];
#pragma unroll
        for (int mi = 0; mi < 2; ++mi)
#pragma unroll
            for (int p = 0; p < 2; ++p) {
                int row = mg * 32 + mi * 16 + (lane >> 2) + p * 8;
                h2v[mi][p] = 0.5f * x2s[row];
                vld[mi][p] = (base + row) < n_tokens;
            }

#pragma unroll
        for (int mi = 0; mi < 2; ++mi)
#pragma unroll
            for (int ni = 0; ni < 4; ++ni)
#pragma unroll
                for (int p = 0; p < 2; ++p)
#pragma unroll
                    for (int ci = 0; ci < 2; ++ci) {
                        float sc = c[mi][ni][ci + 2 * p] - h2v[mi][p];
                        c[mi][ni][ci + 2 * p] = vld[mi][p] ? sc : NEGINF;
                    }

        float mloc[4][2];
#pragma unroll
        for (int ni = 0; ni < 4; ++ni)
#pragma unroll
            for (int ci = 0; ci < 2; ++ci) {
                float m = fmaxf(fmaxf(c[0][ni][ci], c[0][ni][ci + 2]),
                                fmaxf(c[1][ni][ci], c[1][ni][ci + 2]));
#pragma unroll
                for (int d = 4; d <= 16; d <<= 1)
                    m = fmaxf(m, __shfl_xor_sync(0xFFFFFFFFu, m, d));
                mloc[ni][ci] = m;
            }

        float thrf[4][2];
#pragma unroll
        for (int ni = 0; ni < 4; ++ni)
#pragma unroll
            for (int ci = 0; ci < 2; ++ci) {
                int cl = nb + ni * 8 + (lane & 3) * 2 + ci;
                uint32_t hi = lds32v(sb + (uint32_t)(OFF_BEST + cl * 8 + 4));
                float b = inv_orderf(hi);                        // NaN if unset
                thrf[ni][ci] = fmaxf(b - EPS, mloc[ni][ci] - TWOEPS);
            }

        uint32_t myMask = 0;
#pragma unroll
        for (int ni = 0; ni < 4; ++ni)
#pragma unroll
            for (int ci = 0; ci < 2; ++ci)
#pragma unroll
                for (int p = 0; p < 2; ++p)
#pragma unroll
                    for (int mi = 0; mi < 2; ++mi)
                        if (c[mi][ni][ci + 2 * p] >= thrf[ni][ci])
                            myMask |= 1u << ((ni << 3) | (ci << 2) | (p << 1) | mi);

        uint32_t active = __ballot_sync(0xFFFFFFFFu, myMask != 0);
        while (active) {
            int src = __ffs(active) - 1;
            active &= active - 1;
            uint32_t m = __shfl_sync(0xFFFFFFFFu, myMask, src);
            while (m) {
                int b = __ffs(m) - 1;
                m &= m - 1;
                int mi = b & 1, p = (b >> 1) & 1, ci = (b >> 2) & 1, ni = b >> 3;
                int row = mg * 32 + mi * 16 + (src >> 2) + p * 8;
                int cl  = nb + ni * 8 + (src & 3) * 2 + ci;
                warp_rescore(sb, cc, buf, row, cl, base, lane, x2s, bestk);
            }
        }
        __syncthreads();      // (c) all stage/XHI/x2s reads done before next iter
    }

    if (tid < N_CLUS)
        g_part[(size_t)bid * N_CLUS + tid] = bestk[tid];
}

// ---------------- gather: reduce 296 partials per cluster, copy winning row ----------------
__global__ void gather_k(const float* __restrict__ x, float* __restrict__ out) {
    __shared__ unsigned long long red[256];
    const int c = blockIdx.x, tid = threadIdx.x;
    unsigned long long v = 0ull;
    if (tid < GRID_MAIN) v = g_part[(size_t)tid * N_CLUS + c];
    if (tid + 256 < GRID_MAIN) {
        unsigned long long o = g_part[(size_t)(tid + 256) * N_CLUS + c];
        if (o > v) v = o;
    }
    red[tid] = v;
    __syncthreads();
#pragma unroll
    for (int s = 128; s > 0; s >>= 1) {
        if (tid < s) { unsigned long long o = red[tid + s]; if (o > red[tid]) red[tid] = o; }
        __syncthreads();
    }
    unsigned int gi = 0xFFFFFFFFu - (unsigned int)(red[0] & 0xFFFFFFFFull);
    if (tid < N_FEAT)
        out[c * N_FEAT + tid] = x[(size_t)gi * N_FEAT + tid];
}

// ---------------- launch ----------------
extern "C" void kernel_launch(void* const* d_in, const int* in_sizes, int n_in,
                              void* d_out, int out_size)
{
    const float* x  = (const float*)d_in[0];
    const float* cc = (const float*)d_in[1];
    int n_tokens = in_sizes[0] / N_FEAT;

    cudaFuncSetAttribute(cluster_hmma, cudaFuncAttributeMaxDynamicSharedMemorySize, SMEM_TOTAL);
    cluster_hmma<<<GRID_MAIN, THREADS, SMEM_TOTAL>>>(x, cc, n_tokens);
    gather_k<<<N_CLUS, 256>>>(x, (float*)d_out);
}